// round 13
// baseline (speedup 1.0000x reference)
#include <cuda_runtime.h>
#include <cuda_bf16.h>
#include <math.h>

typedef unsigned long long ull;

// ---------- packed f32x2 helpers (sm_103a) ----------
__device__ __forceinline__ ull pk2(float x) {
    ull r; asm("mov.b64 %0, {%1, %1};" : "=l"(r) : "f"(x)); return r;
}
__device__ __forceinline__ ull pkf2(float lo, float hi) {
    ull r; asm("mov.b64 %0, {%1, %2};" : "=l"(r) : "f"(lo), "f"(hi)); return r;
}
__device__ __forceinline__ void fma2(ull& d, ull a, ull b) {
    asm("fma.rn.f32x2 %0, %1, %2, %0;" : "+l"(d) : "l"(a), "l"(b));
}
__device__ __forceinline__ void mul2(ull& d, ull a) {
    asm("mul.rn.f32x2 %0, %1, %0;" : "+l"(d) : "l"(a));
}
__device__ __forceinline__ void unpk2(ull v, float& lo, float& hi) {
    asm("mov.b64 {%0, %1}, %2;" : "=f"(lo), "=f"(hi) : "l"(v));
}
// raw MUFU.EX2 (operand pre-scaled by log2e -> same path __expf takes,
// minus its hidden FMUL)
__device__ __forceinline__ float ex2(float x) {
    float y; asm("ex2.approx.f32 %0, %1;" : "=f"(y) : "f"(x)); return y;
}

// ---------- problem constants ----------
#define BATCH 2
#define SEQ   2048
#define DMODEL 1024
#define NHEADS 16
#define DK    64
#define MTOT  (BATCH * SEQ)        // 4096

// Q scale folded with log2(e): (1/sqrt(64)) * 1.4426950408889634
#define QSCALE 0.18033688f

// GEMM smem strides (in floats):
//  - Ad rows hold the A tile DUPLICATED elementwise ([2m] and [2m+1] = a_m),
//    so LDS.128 yields ready {a,a} pairs for fma.rn.f32x2 -> no MOV dup tax.
//    Staging writes the {a,a} pairs as single 8B stores (STS.64).
//  - Bs stride 132: staging-conflict pad (non-duplicated B tile).
#define ADS 260
#define BSS 132
#define AD_FLOATS (2 * 16 * ADS)                 // 8320 floats
#define GEMM_SMEM_BYTES ((AD_FLOATS + 2 * 16 * BSS) * 4)  // 50,176 B

// Attention smem: Qd duplicated 64x128 (32K), KPd 64x128 (32K: K tile at
// stride 64 in the first half, then P DUPLICATED at stride 128), Vs 64x64
// (16K) -> 80 KB dynamic, 2 CTAs/SM.
#define QD_FLOATS  (64 * 128)
#define KPD_FLOATS (64 * 128)
#define VS_FLOATS  (64 * 64)
#define ATTN_SMEM_BYTES ((QD_FLOATS + KPD_FLOATS + VS_FLOATS) * 4)  // 81,920 B

// ---------- scratch (device globals; no runtime allocation) ----------
__device__ float g_Q[MTOT * DMODEL];   // stored as [b][h][d][s]  (transposed)
__device__ float g_K[MTOT * DMODEL];   // stored as [b][h][d][s]  (transposed)
__device__ float g_V[MTOT * DMODEL];   // stored as [b][s][h][d]  (natural)
__device__ float g_O[MTOT * DMODEL];   // stored as [b][s][h][d]  (natural)

// duplicated-pair store: one 8-byte STS instead of two scalar STS
__device__ __forceinline__ void st_dup2(float* p, float v) {
    *(float2*)p = make_float2(v, v);
}

// =====================================================================
// GEMM: C = A @ W^T.   A: [M=4096, K=1024] row-major. W: [N=1024, K=1024]
// row-major (torch [out,in]).  Block tile 128x128, K-tile 16, 256 threads,
// 8x8 per-thread register tile computed with fma.rn.f32x2.
// Double-buffered DYNAMIC smem (ping-pong): ONE __syncthreads per K-tile.
// A tile stored duplicated -> inner loop has ZERO MOVs: 6 LDS.128 +
// 32 FFMA2 per kk. A staging uses STS.64 pair stores.
// If (blockIdx.z < ntrans) the output is written transposed per-batch:
//   C[(b*1024 + n)*2048 + s]  where m = b*2048 + s   (i.e. [b][h][d][s]).
// =====================================================================
__global__ __launch_bounds__(256, 2)
void gemm_k(const float* __restrict__ A,
            const float* __restrict__ W0, const float* __restrict__ W1,
            const float* __restrict__ W2,
            float* __restrict__ C0, float* __restrict__ C1, float* __restrict__ C2,
            int ntrans)
{
    const int z = blockIdx.z;
    const float* __restrict__ W = (z == 0) ? W0 : (z == 1) ? W1 : W2;
    float* __restrict__ C       = (z == 0) ? C0 : (z == 1) ? C1 : C2;
    const bool trans = (z < ntrans);

    extern __shared__ __align__(16) float dsm[];
    typedef float AdRow[16][ADS];
    typedef float BsRow[16][BSS];
    AdRow* Ad = (AdRow*)dsm;                 // Ad[2][16][ADS]
    BsRow* Bs = (BsRow*)(dsm + AD_FLOATS);   // Bs[2][16][BSS]

    const int tid = threadIdx.x;
    const int tn = tid & 15;          // 0..15
    const int tm = tid >> 4;          // 0..15
    const int bm = blockIdx.y * 128;
    const int bn = blockIdx.x * 128;

    const int lrow = tid >> 2;        // 0..63
    const int lk   = (tid & 3) * 4;   // 0,4,8,12

    const float* Ap = A + (size_t)(bm + lrow) * 1024 + lk;
    const float* Wp = W + (size_t)(bn + lrow) * 1024 + lk;

    ull acc[8][4];
#pragma unroll
    for (int i = 0; i < 8; i++)
#pragma unroll
        for (int j = 0; j < 4; j++) acc[i][j] = 0ull;

    // prologue: tile 0 -> regs -> smem buffer 0 (A duplicated, STS.64)
    {
        float4 ra0 = *(const float4*)(Ap);
        float4 ra1 = *(const float4*)(Ap + 64 * 1024);
        float4 rb0 = *(const float4*)(Wp);
        float4 rb1 = *(const float4*)(Wp + 64 * 1024);
        const int d0 = 2 * lrow, d1 = 2 * lrow + 128;
        st_dup2(&Ad[0][lk + 0][d0], ra0.x);
        st_dup2(&Ad[0][lk + 1][d0], ra0.y);
        st_dup2(&Ad[0][lk + 2][d0], ra0.z);
        st_dup2(&Ad[0][lk + 3][d0], ra0.w);
        st_dup2(&Ad[0][lk + 0][d1], ra1.x);
        st_dup2(&Ad[0][lk + 1][d1], ra1.y);
        st_dup2(&Ad[0][lk + 2][d1], ra1.z);
        st_dup2(&Ad[0][lk + 3][d1], ra1.w);
        Bs[0][lk + 0][lrow]      = rb0.x; Bs[0][lk + 1][lrow]      = rb0.y;
        Bs[0][lk + 2][lrow]      = rb0.z; Bs[0][lk + 3][lrow]      = rb0.w;
        Bs[0][lk + 0][lrow + 64] = rb1.x; Bs[0][lk + 1][lrow + 64] = rb1.y;
        Bs[0][lk + 2][lrow + 64] = rb1.z; Bs[0][lk + 3][lrow + 64] = rb1.w;
    }
    __syncthreads();

#pragma unroll 2
    for (int kt = 0; kt < 64; kt++) {
        const int cur = kt & 1;
        const int nxt = cur ^ 1;

        float4 ra0, ra1, rb0, rb1;
        if (kt < 63) {               // prefetch next tile into registers
            Ap += 16; Wp += 16;
            ra0 = *(const float4*)(Ap);
            ra1 = *(const float4*)(Ap + 64 * 1024);
            rb0 = *(const float4*)(Wp);
            rb1 = *(const float4*)(Wp + 64 * 1024);
        }

        // compute from buffer `cur`: 6 LDS.128 + 32 FFMA2 per kk, no MOVs.
#pragma unroll
        for (int kk = 0; kk < 16; kk++) {
            ulonglong2 A0 = *(const ulonglong2*)&Ad[cur][kk][8 * tm];
            ulonglong2 A1 = *(const ulonglong2*)&Ad[cur][kk][8 * tm + 4];
            ulonglong2 A2 = *(const ulonglong2*)&Ad[cur][kk][128 + 8 * tm];
            ulonglong2 A3 = *(const ulonglong2*)&Ad[cur][kk][128 + 8 * tm + 4];
            ulonglong2 B0 = *(const ulonglong2*)&Bs[cur][kk][tn * 4];
            ulonglong2 B1 = *(const ulonglong2*)&Bs[cur][kk][64 + tn * 4];
            ull ad[8] = {A0.x, A0.y, A1.x, A1.y, A2.x, A2.y, A3.x, A3.y};
#pragma unroll
            for (int i = 0; i < 8; i++) {
                fma2(acc[i][0], ad[i], B0.x);
                fma2(acc[i][1], ad[i], B0.y);
                fma2(acc[i][2], ad[i], B1.x);
                fma2(acc[i][3], ad[i], B1.y);
            }
        }

        if (kt < 63) {
            const int d0 = 2 * lrow, d1 = 2 * lrow + 128;
            st_dup2(&Ad[nxt][lk + 0][d0], ra0.x);
            st_dup2(&Ad[nxt][lk + 1][d0], ra0.y);
            st_dup2(&Ad[nxt][lk + 2][d0], ra0.z);
            st_dup2(&Ad[nxt][lk + 3][d0], ra0.w);
            st_dup2(&Ad[nxt][lk + 0][d1], ra1.x);
            st_dup2(&Ad[nxt][lk + 1][d1], ra1.y);
            st_dup2(&Ad[nxt][lk + 2][d1], ra1.z);
            st_dup2(&Ad[nxt][lk + 3][d1], ra1.w);
            Bs[nxt][lk + 0][lrow]      = rb0.x; Bs[nxt][lk + 1][lrow]      = rb0.y;
            Bs[nxt][lk + 2][lrow]      = rb0.z; Bs[nxt][lk + 3][lrow]      = rb0.w;
            Bs[nxt][lk + 0][lrow + 64] = rb1.x; Bs[nxt][lk + 1][lrow + 64] = rb1.y;
            Bs[nxt][lk + 2][lrow + 64] = rb1.z; Bs[nxt][lk + 3][lrow + 64] = rb1.w;
            __syncthreads();
        }
    }

    // epilogue
    if (!trans) {
#pragma unroll
        for (int i = 0; i < 8; i++) {
            const int m = bm + ((i < 4) ? (tm * 4 + i) : (64 + tm * 4 + (i - 4)));
            float c0, c1, c2, c3, c4, c5, c6, c7;
            unpk2(acc[i][0], c0, c1); unpk2(acc[i][1], c2, c3);
            unpk2(acc[i][2], c4, c5); unpk2(acc[i][3], c6, c7);
            *(float4*)(C + (size_t)m * 1024 + bn + tn * 4)      = make_float4(c0, c1, c2, c3);
            *(float4*)(C + (size_t)m * 1024 + bn + 64 + tn * 4) = make_float4(c4, c5, c6, c7);
        }
    } else {
#pragma unroll
        for (int half = 0; half < 2; half++) {
            float cv[4][8];
#pragma unroll
            for (int i = 0; i < 4; i++) {
                const int r = half * 4 + i;
                unpk2(acc[r][0], cv[i][0], cv[i][1]);
                unpk2(acc[r][1], cv[i][2], cv[i][3]);
                unpk2(acc[r][2], cv[i][4], cv[i][5]);
                unpk2(acc[r][3], cv[i][6], cv[i][7]);
            }
            const int m0 = bm + half * 64 + tm * 4;
            const int bb = m0 >> 11;
            const int s0 = m0 & 2047;
            float* Cb = C + ((size_t)bb * 1024) * 2048 + s0;
#pragma unroll
            for (int j = 0; j < 8; j++) {
                const int n = bn + ((j < 4) ? (tn * 4 + j) : (64 + tn * 4 + (j - 4)));
                *(float4*)(Cb + (size_t)n * 2048) =
                    make_float4(cv[0][j], cv[1][j], cv[2][j], cv[3][j]);
            }
        }
    }
}

// =====================================================================
// Causal flash attention, fp32, BLOCK_Q = BLOCK_K = 64, dk = 64.
// Qt/Kt are [b][h][d][s]; V/O are [b][s][h][d]. 256 threads.
// Grid is (h=16, b=2, qtile=32) with qtile on z (slowest) -> LPT order.
// Softmax in exp2 domain (Q pre-scaled by log2e/8, raw MUFU.EX2).
// BOTH fma phases MOV-free (Q and P duplicated in smem).
// K/V global loads SOFTWARE-PIPELINED one tile ahead in registers.
// 80 KB dynamic smem, 2 CTAs/SM.
// =====================================================================
__global__ __launch_bounds__(256)
void attn_k(const float* __restrict__ Qt, const float* __restrict__ Kt,
            const float* __restrict__ V, float* __restrict__ O)
{
    extern __shared__ __align__(16) float asm_[];
    float* Qd  = asm_;                            // [64][128] Q duplicated
    float* KPd = asm_ + QD_FLOATS;                // K tile [d][64] (first half), then P duplicated [i][128]
    float* Vs  = asm_ + QD_FLOATS + KPD_FLOATS;   // [64][64]: [j][d]

    const int tid = threadIdx.x;
    const int tc = tid & 15;          // 0..15
    const int tr = tid >> 4;          // 0..15
    const int h  = blockIdx.x;
    const int b  = blockIdx.y;
    const int qt = (int)(gridDim.z - 1) - (int)blockIdx.z;  // LPT: heavy first

    const size_t qkbase = ((size_t)b * 1024 + h * 64) * 2048;
    const size_t vbase  = ((size_t)b * 2048) * 1024 + h * 64;

    // load Q tile (scaled by log2e/sqrt(dk)), write DUPLICATED
#pragma unroll
    for (int it = 0; it < 4; it++) {
        int d  = it * 16 + tr;
        int i4 = tc * 4;
        float4 v4 = *(const float4*)(Qt + qkbase + (size_t)d * 2048 + qt * 64 + i4);
        v4.x *= QSCALE; v4.y *= QSCALE; v4.z *= QSCALE; v4.w *= QSCALE;
        float* row = Qd + d * 128 + 2 * i4;
        *(float4*)(row)     = make_float4(v4.x, v4.x, v4.y, v4.y);
        *(float4*)(row + 4) = make_float4(v4.z, v4.z, v4.w, v4.w);
    }

    // prologue: prefetch K/V tile 0 into registers
    float4 rk[4], rv[4];
#pragma unroll
    for (int it = 0; it < 4; it++) {
        int d = it * 16 + tr;
        rk[it] = *(const float4*)(Kt + qkbase + (size_t)d * 2048 + tc * 4);
        int j = it * 16 + tr;
        rv[it] = *(const float4*)(V + vbase + (size_t)j * 1024 + tc * 4);
    }

    ull o2[4][2];
    float mrow[4], lrow[4];
#pragma unroll
    for (int ii = 0; ii < 4; ii++) {
        o2[ii][0] = 0ull; o2[ii][1] = 0ull;
        mrow[ii] = -1e30f; lrow[ii] = 0.0f;
    }

    for (int kt = 0; kt <= qt; kt++) {
        __syncthreads();    // prior PV reads of KPd/Vs complete (orders Qd on iter 0)

        // store the pre-fetched tile (registers -> smem; no latency wait)
#pragma unroll
        for (int it = 0; it < 4; it++) {
            int d = it * 16 + tr;
            *(float4*)&KPd[d * 64 + tc * 4] = rk[it];
            int j = it * 16 + tr;
            *(float4*)&Vs[j * 64 + tc * 4] = rv[it];
        }

        // issue next-tile LDGs (hidden behind this iteration's compute)
        if (kt < qt) {
            const int nk = kt + 1;
#pragma unroll
            for (int it = 0; it < 4; it++) {
                int d = it * 16 + tr;
                rk[it] = *(const float4*)(Kt + qkbase + (size_t)d * 2048 + nk * 64 + tc * 4);
                int j = it * 16 + tr;
                rv[it] = *(const float4*)(V + vbase + (size_t)(nk * 64 + j) * 1024 + tc * 4);
            }
        }
        __syncthreads();

        // S = Q K^T: per d, 3 LDS.128 + 8 FFMA2, zero MOVs.
        ull s2[4][2];
#pragma unroll
        for (int ii = 0; ii < 4; ii++) { s2[ii][0] = 0ull; s2[ii][1] = 0ull; }
#pragma unroll 8
        for (int d = 0; d < 64; d++) {
            ulonglong2 Qa = *(const ulonglong2*)&Qd[d * 128 + 8 * tr];       // {q0,q0},{q1,q1}
            ulonglong2 Qb = *(const ulonglong2*)&Qd[d * 128 + 8 * tr + 4];   // {q2,q2},{q3,q3}
            ulonglong2 Kp = *(const ulonglong2*)&KPd[d * 64 + tc * 4];       // {k0,k1},{k2,k3}
            ull qd[4] = {Qa.x, Qa.y, Qb.x, Qb.y};
#pragma unroll
            for (int i = 0; i < 4; i++) {
                fma2(s2[i][0], qd[i], Kp.x);
                fma2(s2[i][1], qd[i], Kp.y);
            }
        }
        __syncthreads();    // all K reads done; KPd may now be overwritten with P

        const bool diag = (kt == qt);
#pragma unroll
        for (int ii = 0; ii < 4; ii++) {
            float s0, s1, s2v, s3;
            unpk2(s2[ii][0], s0, s1);
            unpk2(s2[ii][1], s2v, s3);
            if (diag) {
                const int qg = tr * 4 + ii;
                const int j0 = tc * 4;
                if (j0 + 0 > qg) s0  = -1e30f;
                if (j0 + 1 > qg) s1  = -1e30f;
                if (j0 + 2 > qg) s2v = -1e30f;
                if (j0 + 3 > qg) s3  = -1e30f;
            }
            float mx = fmaxf(fmaxf(s0, s1), fmaxf(s2v, s3));
            mx = fmaxf(mx, __shfl_xor_sync(0xffffffffu, mx, 1));
            mx = fmaxf(mx, __shfl_xor_sync(0xffffffffu, mx, 2));
            mx = fmaxf(mx, __shfl_xor_sync(0xffffffffu, mx, 4));
            mx = fmaxf(mx, __shfl_xor_sync(0xffffffffu, mx, 8));
            const float mnew  = fmaxf(mrow[ii], mx);
            const float alpha = ex2(mrow[ii] - mnew);   // exp2 domain
            mrow[ii] = mnew;
            float p0 = ex2(s0 - mnew);
            float p1 = ex2(s1 - mnew);
            float p2 = ex2(s2v - mnew);
            float p3 = ex2(s3 - mnew);
            float sum = p0 + p1 + p2 + p3;
            sum += __shfl_xor_sync(0xffffffffu, sum, 1);
            sum += __shfl_xor_sync(0xffffffffu, sum, 2);
            sum += __shfl_xor_sync(0xffffffffu, sum, 4);
            sum += __shfl_xor_sync(0xffffffffu, sum, 8);
            lrow[ii] = lrow[ii] * alpha + sum;
            ull ap = pk2(alpha);
            mul2(o2[ii][0], ap);
            mul2(o2[ii][1], ap);
            // store P DUPLICATED: row stride 128, cols 2j / 2j+1
            float* prow = KPd + (tr * 4 + ii) * 128 + 8 * tc;
            *(float4*)(prow)     = make_float4(p0, p0, p1, p1);
            *(float4*)(prow + 4) = make_float4(p2, p2, p3, p3);
        }
        __syncthreads();    // P fully written

        // O += P V  (j-blocked by 4; P pairs pre-duplicated -> zero MOVs)
#pragma unroll 4
        for (int j0 = 0; j0 < 64; j0 += 4) {
            ulonglong2 v[4];
#pragma unroll
            for (int jj = 0; jj < 4; jj++)
                v[jj] = *(const ulonglong2*)&Vs[(j0 + jj) * 64 + tc * 4];
#pragma unroll
            for (int ii = 0; ii < 4; ii++) {
                const float* prow = KPd + (tr * 4 + ii) * 128 + 2 * j0;
                ulonglong2 P0 = *(const ulonglong2*)(prow);      // {p0,p0},{p1,p1}
                ulonglong2 P1 = *(const ulonglong2*)(prow + 4);  // {p2,p2},{p3,p3}
                fma2(o2[ii][0], P0.x, v[0].x); fma2(o2[ii][1], P0.x, v[0].y);
                fma2(o2[ii][0], P0.y, v[1].x); fma2(o2[ii][1], P0.y, v[1].y);
                fma2(o2[ii][0], P1.x, v[2].x); fma2(o2[ii][1], P1.x, v[2].y);
                fma2(o2[ii][0], P1.y, v[3].x); fma2(o2[ii][1], P1.y, v[3].y);
            }
        }
    }

    // normalize and store O[b][s][h][d]
#pragma unroll
    for (int ii = 0; ii < 4; ii++) {
        const float inv = 1.0f / lrow[ii];
        float o0, o1, o2v, o3;
        unpk2(o2[ii][0], o0, o1);
        unpk2(o2[ii][1], o2v, o3);
        const int qg = qt * 64 + tr * 4 + ii;
        *(float4*)(O + ((size_t)b * 2048 + qg) * 1024 + h * 64 + tc * 4) =
            make_float4(o0 * inv, o1 * inv, o2v * inv, o3 * inv);
    }
}

// =====================================================================
// launch
// =====================================================================
extern "C" void kernel_launch(void* const* d_in, const int* in_sizes, int n_in,
                              void* d_out, int out_size)
{
    const float* x  = (const float*)d_in[0];
    const float* wq = (const float*)d_in[1];
    const float* wk = (const float*)d_in[2];
    const float* wv = (const float*)d_in[3];
    const float* wo = (const float*)d_in[4];
    float* out = (float*)d_out;

    float *gQ, *gK, *gV, *gO;
    cudaGetSymbolAddress((void**)&gQ, g_Q);
    cudaGetSymbolAddress((void**)&gK, g_K);
    cudaGetSymbolAddress((void**)&gV, g_V);
    cudaGetSymbolAddress((void**)&gO, g_O);

    // allow >48KB dynamic smem (host-side attrs; graph-legal)
    cudaFuncSetAttribute(gemm_k, cudaFuncAttributeMaxDynamicSharedMemorySize,
                         GEMM_SMEM_BYTES);
    cudaFuncSetAttribute(attn_k, cudaFuncAttributeMaxDynamicSharedMemorySize,
                         ATTN_SMEM_BYTES);

    // Q/K projections write [b][h][d][s] (trans), V writes [b][s][h][d]
    gemm_k<<<dim3(8, 32, 3), 256, GEMM_SMEM_BYTES>>>(x, wq, wk, wv, gQ, gK, gV, /*ntrans=*/2);

    // causal flash attention — LPT grid: qtile on z (slowest-varying)
    attn_k<<<dim3(16, 2, 32), 256, ATTN_SMEM_BYTES>>>(gQ, gK, gV, gO);

    // output projection -> d_out
    gemm_k<<<dim3(8, 32, 1), 256, GEMM_SMEM_BYTES>>>(gO, wo, wo, wo, out, out, out, /*ntrans=*/0);
}

// round 16
// speedup vs baseline: 1.4135x; 1.4135x over previous
#include <cuda_runtime.h>
#include <cuda_bf16.h>
#include <math.h>
#include <stdint.h>

typedef unsigned long long ull;

// ================= packed f32x2 helpers (attention) =================
__device__ __forceinline__ ull pk2(float x) {
    ull r; asm("mov.b64 %0, {%1, %1};" : "=l"(r) : "f"(x)); return r;
}
__device__ __forceinline__ void fma2(ull& d, ull a, ull b) {
    asm("fma.rn.f32x2 %0, %1, %2, %0;" : "+l"(d) : "l"(a), "l"(b));
}
__device__ __forceinline__ void mul2(ull& d, ull a) {
    asm("mul.rn.f32x2 %0, %1, %0;" : "+l"(d) : "l"(a));
}
__device__ __forceinline__ void unpk2(ull v, float& lo, float& hi) {
    asm("mov.b64 {%0, %1}, %2;" : "=f"(lo), "=f"(hi) : "l"(v));
}
__device__ __forceinline__ float ex2(float x) {
    float y; asm("ex2.approx.f32 %0, %1;" : "=f"(y) : "f"(x)); return y;
}

// ================= mma.sync + cp.async helpers (sm_80+ baseline) ============
__device__ __forceinline__ uint32_t smem_u32(const void* p) {
    uint32_t a;
    asm("{ .reg .u64 t; cvta.to.shared.u64 t, %1; cvt.u32.u64 %0, t; }" : "=r"(a) : "l"(p));
    return a;
}
__device__ __forceinline__ void mma16816(float& c0, float& c1, float& c2, float& c3,
                                         uint32_t a0, uint32_t a1, uint32_t a2, uint32_t a3,
                                         uint32_t b0, uint32_t b1) {
    asm volatile("mma.sync.aligned.m16n8k16.row.col.f32.bf16.bf16.f32 "
        "{%0,%1,%2,%3}, {%4,%5,%6,%7}, {%8,%9}, {%0,%1,%2,%3};"
        : "+f"(c0), "+f"(c1), "+f"(c2), "+f"(c3)
        : "r"(a0), "r"(a1), "r"(a2), "r"(a3), "r"(b0), "r"(b1));
}
__device__ __forceinline__ void cp16(uint32_t dst, const void* src) {
    asm volatile("cp.async.ca.shared.global [%0], [%1], 16;" :: "r"(dst), "l"(src));
}
#define CP_COMMIT() asm volatile("cp.async.commit_group;" ::: "memory")
#define CP_WAIT1()  asm volatile("cp.async.wait_group 1;" ::: "memory")
#define CP_WAIT0()  asm volatile("cp.async.wait_group 0;" ::: "memory")

// ================= problem constants =================
#define BATCH 2
#define SEQ   2048
#define DMODEL 1024
#define NHEADS 16
#define MTOT  (BATCH * SEQ)            // 4096
#define NELEM (MTOT * DMODEL)
#define WELEM (DMODEL * DMODEL)
#define QSCALE 0.18033688f             // (1/8) * log2(e)

// GEMM smem: 4 tiles (Ph,Pl,Qh,Ql) of 128 x 32 halves, row stride 40 halves
// (pad -> conflict-free frag loads), double buffered.
#define SH 40                          // halves per row
#define SW 20                          // words per row
#define TILE_H (128 * SH)              // 5120 halves per tile
#define BUF_H  (4 * TILE_H)            // 20480 halves per buffer
#define GEMM_SMEM_BYTES (2 * BUF_H * 2)  // 81920 B

// attention smem (80 KB, unchanged)
#define QD_FLOATS  (64 * 128)
#define KPD_FLOATS (64 * 128)
#define VS_FLOATS  (64 * 64)
#define ATTN_SMEM_BYTES ((QD_FLOATS + KPD_FLOATS + VS_FLOATS) * 4)

// ================= scratch =================
__device__ float g_Q[NELEM];   // [b][h][d][s]
__device__ float g_K[NELEM];   // [b][h][d][s]
__device__ float g_V[NELEM];   // [b][s][h][d]
__device__ float g_O[NELEM];   // [b][s][h][d]
__device__ __nv_bfloat16 g_xh[NELEM], g_xl[NELEM];
__device__ __nv_bfloat16 g_oh[NELEM], g_ol[NELEM];
__device__ __nv_bfloat16 g_wh[4 * WELEM], g_wl[4 * WELEM];  // wq, wk, wv, wo

// ================= bf16 hi/lo split =================
__global__ __launch_bounds__(256)
void split_k(const float4* __restrict__ src, __nv_bfloat162* __restrict__ hi,
             __nv_bfloat162* __restrict__ lo, int n4)
{
    int i = blockIdx.x * 256 + threadIdx.x;
    if (i >= n4) return;
    float4 v = src[i];
    __nv_bfloat16 h0 = __float2bfloat16(v.x), h1 = __float2bfloat16(v.y);
    __nv_bfloat16 h2 = __float2bfloat16(v.z), h3 = __float2bfloat16(v.w);
    __nv_bfloat16 l0 = __float2bfloat16(v.x - __bfloat162float(h0));
    __nv_bfloat16 l1 = __float2bfloat16(v.y - __bfloat162float(h1));
    __nv_bfloat16 l2 = __float2bfloat16(v.z - __bfloat162float(h2));
    __nv_bfloat16 l3 = __float2bfloat16(v.w - __bfloat162float(h3));
    __nv_bfloat162 a, b, c, d;
    a.x = h0; a.y = h1; b.x = h2; b.y = h3;
    c.x = l0; c.y = l1; d.x = l2; d.y = l3;
    hi[2 * i] = a; hi[2 * i + 1] = b;
    lo[2 * i] = c; lo[2 * i + 1] = d;
}

// ================= mma.sync bf16-split GEMM =================
// C = act @ Wz^T in 128(P) x 128(Q) tiles, K = 1024 in 32 chunks of 32.
// Split: D += Ph*Qh + Ph*Ql + Pl*Qh (fp32 accumulate in registers).
// trans (z<ntrans): P = W rows (n), Q = act rows (s); C[(bb*1024+n)*2048+s]
// natural:          P = act rows (m), Q = W rows (n); C[m*1024+n]
// 8 warps: warp_m = wid&1 (64 P-rows), warp_n = wid>>1 (32 Q-cols).
// cp.async double-buffered staging; frag loads are padded-stride LDS.32.
__global__ __launch_bounds__(256)
void mma_gemm(const __nv_bfloat16* __restrict__ ah, const __nv_bfloat16* __restrict__ al,
              const __nv_bfloat16* __restrict__ wh, const __nv_bfloat16* __restrict__ wl,
              float* __restrict__ C0, float* __restrict__ C1, float* __restrict__ C2,
              int ntrans)
{
    extern __shared__ __align__(16) __nv_bfloat16 smh[];
    const uint32_t sb = smem_u32(smh);

    const int z = blockIdx.z;
    float* __restrict__ C = (z == 0) ? C0 : (z == 1) ? C1 : C2;
    const __nv_bfloat16* __restrict__ whz = wh + (size_t)z * WELEM;
    const __nv_bfloat16* __restrict__ wlz = wl + (size_t)z * WELEM;
    const bool trans = (z < ntrans);

    const int bid = blockIdx.x;
    const int tid = threadIdx.x;
    const int wid = tid >> 5;
    const int lid = tid & 31;
    const int g = lid >> 2;        // 0..7
    const int t = lid & 3;         // 0..3

    int p_base, q_base;
    const __nv_bfloat16 *Psrc[2], *Qsrc[2];
    if (trans) {
        p_base = (bid & 7) * 128;  q_base = (bid >> 3) * 128;
        Psrc[0] = whz; Psrc[1] = wlz; Qsrc[0] = ah; Qsrc[1] = al;
    } else {
        p_base = (bid & 31) * 128; q_base = (bid >> 5) * 128;
        Psrc[0] = ah; Psrc[1] = al; Qsrc[0] = whz; Qsrc[1] = wlz;
    }

    const int warp_m = wid & 1;    // 0..1
    const int warp_n = wid >> 1;   // 0..3

    // stage one K-chunk (32 halves wide) into buffer `buf` via cp.async
    auto stage = [&](int kc, int buf) {
        const uint32_t dbase = sb + (uint32_t)buf * BUF_H * 2;
#pragma unroll
        for (int i = 0; i < 8; i++) {
            const int c  = tid + i * 256;      // 0..2047
            const int tt = c >> 9;             // tile 0..3
            const int ci = c & 511;
            const int row = ci >> 2;
            const int seg = ci & 3;
            const __nv_bfloat16* src =
                (tt < 2 ? Psrc[tt] : Qsrc[tt - 2])
                + (size_t)((tt < 2 ? p_base : q_base) + row) * 1024 + kc * 32 + seg * 8;
            const uint32_t dst = dbase + (uint32_t)(tt * TILE_H + row * SH + seg * 8) * 2;
            cp16(dst, src);
        }
        CP_COMMIT();
    };

    float acc[4][4][4];
#pragma unroll
    for (int mt = 0; mt < 4; mt++)
#pragma unroll
        for (int nt = 0; nt < 4; nt++)
#pragma unroll
            for (int k = 0; k < 4; k++) acc[mt][nt][k] = 0.0f;

    stage(0, 0);

    for (int kc = 0; kc < 32; kc++) {
        const int buf = kc & 1;
        if (kc < 31) { stage(kc + 1, buf ^ 1); CP_WAIT1(); }
        else         { CP_WAIT0(); }
        __syncthreads();

        const uint32_t* bw = (const uint32_t*)(smh + buf * BUF_H);
        const uint32_t* Phw = bw;
        const uint32_t* Plw = bw + TILE_H / 2;
        const uint32_t* Qhw = bw + TILE_H;
        const uint32_t* Qlw = bw + 3 * (TILE_H / 2);

#pragma unroll
        for (int ks = 0; ks < 2; ks++) {
            const int kw = ks * 8;   // word offset of this k16 within the row

            uint32_t Ah[4][4], Al[4][4], Bh[4][2], Bl[4][2];
#pragma unroll
            for (int mt = 0; mt < 4; mt++) {
                const int r0 = (warp_m * 64 + mt * 16 + g) * SW;
                const int r1 = r0 + 8 * SW;
                Ah[mt][0] = Phw[r0 + kw + t];     Ah[mt][1] = Phw[r1 + kw + t];
                Ah[mt][2] = Phw[r0 + kw + 4 + t]; Ah[mt][3] = Phw[r1 + kw + 4 + t];
                Al[mt][0] = Plw[r0 + kw + t];     Al[mt][1] = Plw[r1 + kw + t];
                Al[mt][2] = Plw[r0 + kw + 4 + t]; Al[mt][3] = Plw[r1 + kw + 4 + t];
            }
#pragma unroll
            for (int nt = 0; nt < 4; nt++) {
                const int rn = (warp_n * 32 + nt * 8 + g) * SW;
                Bh[nt][0] = Qhw[rn + kw + t]; Bh[nt][1] = Qhw[rn + kw + 4 + t];
                Bl[nt][0] = Qlw[rn + kw + t]; Bl[nt][1] = Qlw[rn + kw + 4 + t];
            }
#pragma unroll
            for (int mt = 0; mt < 4; mt++)
#pragma unroll
                for (int nt = 0; nt < 4; nt++) {
                    float* c = acc[mt][nt];
                    mma16816(c[0], c[1], c[2], c[3],
                             Ah[mt][0], Ah[mt][1], Ah[mt][2], Ah[mt][3],
                             Bh[nt][0], Bh[nt][1]);
                    mma16816(c[0], c[1], c[2], c[3],
                             Ah[mt][0], Ah[mt][1], Ah[mt][2], Ah[mt][3],
                             Bl[nt][0], Bl[nt][1]);
                    mma16816(c[0], c[1], c[2], c[3],
                             Al[mt][0], Al[mt][1], Al[mt][2], Al[mt][3],
                             Bh[nt][0], Bh[nt][1]);
                }
        }
        __syncthreads();
    }

    // epilogue: thread owns rows (g, g+8) per m-tile, cols (2t, 2t+1) per n-tile
#pragma unroll
    for (int mt = 0; mt < 4; mt++) {
        const int row = p_base + warp_m * 64 + mt * 16 + g;
#pragma unroll
        for (int nt = 0; nt < 4; nt++) {
            const int col = q_base + warp_n * 32 + nt * 8 + 2 * t;
            const float* c = acc[mt][nt];
            if (trans) {
                const int bb = col >> 11;
                const int s_in = col & 2047;
                float* o0 = C + ((size_t)bb * 1024 + row) * 2048 + s_in;
                *(float2*)o0            = make_float2(c[0], c[1]);
                *(float2*)(o0 + 8 * 2048) = make_float2(c[2], c[3]);
            } else {
                float* o0 = C + (size_t)row * 1024 + col;
                *(float2*)o0            = make_float2(c[0], c[1]);
                *(float2*)(o0 + 8 * 1024) = make_float2(c[2], c[3]);
            }
        }
    }
}

// ================= causal flash attention (unchanged, PASSING) =================
__global__ __launch_bounds__(256)
void attn_k(const float* __restrict__ Qt, const float* __restrict__ Kt,
            const float* __restrict__ V, float* __restrict__ O)
{
    extern __shared__ __align__(16) float asm_[];
    float* Qd  = asm_;
    float* KPd = asm_ + QD_FLOATS;
    float* Vs  = asm_ + QD_FLOATS + KPD_FLOATS;

    const int tid = threadIdx.x;
    const int tc = tid & 15;
    const int tr = tid >> 4;
    const int h  = blockIdx.x;
    const int b  = blockIdx.y;
    const int qt = (int)(gridDim.z - 1) - (int)blockIdx.z;

    const size_t qkbase = ((size_t)b * 1024 + h * 64) * 2048;
    const size_t vbase  = ((size_t)b * 2048) * 1024 + h * 64;

#pragma unroll
    for (int it = 0; it < 4; it++) {
        int d  = it * 16 + tr;
        int i4 = tc * 4;
        float4 v4 = *(const float4*)(Qt + qkbase + (size_t)d * 2048 + qt * 64 + i4);
        v4.x *= QSCALE; v4.y *= QSCALE; v4.z *= QSCALE; v4.w *= QSCALE;
        float* row = Qd + d * 128 + 2 * i4;
        *(float4*)(row)     = make_float4(v4.x, v4.x, v4.y, v4.y);
        *(float4*)(row + 4) = make_float4(v4.z, v4.z, v4.w, v4.w);
    }

    float4 rk[4], rv[4];
#pragma unroll
    for (int it = 0; it < 4; it++) {
        int d = it * 16 + tr;
        rk[it] = *(const float4*)(Kt + qkbase + (size_t)d * 2048 + tc * 4);
        int j = it * 16 + tr;
        rv[it] = *(const float4*)(V + vbase + (size_t)j * 1024 + tc * 4);
    }

    ull o2[4][2];
    float mrow[4], lrow[4];
#pragma unroll
    for (int ii = 0; ii < 4; ii++) {
        o2[ii][0] = 0ull; o2[ii][1] = 0ull;
        mrow[ii] = -1e30f; lrow[ii] = 0.0f;
    }

    for (int kt = 0; kt <= qt; kt++) {
        __syncthreads();
#pragma unroll
        for (int it = 0; it < 4; it++) {
            int d = it * 16 + tr;
            *(float4*)&KPd[d * 64 + tc * 4] = rk[it];
            int j = it * 16 + tr;
            *(float4*)&Vs[j * 64 + tc * 4] = rv[it];
        }
        if (kt < qt) {
            const int nk = kt + 1;
#pragma unroll
            for (int it = 0; it < 4; it++) {
                int d = it * 16 + tr;
                rk[it] = *(const float4*)(Kt + qkbase + (size_t)d * 2048 + nk * 64 + tc * 4);
                int j = it * 16 + tr;
                rv[it] = *(const float4*)(V + vbase + (size_t)(nk * 64 + j) * 1024 + tc * 4);
            }
        }
        __syncthreads();

        ull s2[4][2];
#pragma unroll
        for (int ii = 0; ii < 4; ii++) { s2[ii][0] = 0ull; s2[ii][1] = 0ull; }
#pragma unroll 8
        for (int d = 0; d < 64; d++) {
            ulonglong2 Qa = *(const ulonglong2*)&Qd[d * 128 + 8 * tr];
            ulonglong2 Qb = *(const ulonglong2*)&Qd[d * 128 + 8 * tr + 4];
            ulonglong2 Kp = *(const ulonglong2*)&KPd[d * 64 + tc * 4];
            ull qd[4] = {Qa.x, Qa.y, Qb.x, Qb.y};
#pragma unroll
            for (int i = 0; i < 4; i++) {
                fma2(s2[i][0], qd[i], Kp.x);
                fma2(s2[i][1], qd[i], Kp.y);
            }
        }
        __syncthreads();

        const bool diag = (kt == qt);
#pragma unroll
        for (int ii = 0; ii < 4; ii++) {
            float s0, s1, s2v, s3;
            unpk2(s2[ii][0], s0, s1);
            unpk2(s2[ii][1], s2v, s3);
            if (diag) {
                const int qg = tr * 4 + ii;
                const int j0 = tc * 4;
                if (j0 + 0 > qg) s0  = -1e30f;
                if (j0 + 1 > qg) s1  = -1e30f;
                if (j0 + 2 > qg) s2v = -1e30f;
                if (j0 + 3 > qg) s3  = -1e30f;
            }
            float mx = fmaxf(fmaxf(s0, s1), fmaxf(s2v, s3));
            mx = fmaxf(mx, __shfl_xor_sync(0xffffffffu, mx, 1));
            mx = fmaxf(mx, __shfl_xor_sync(0xffffffffu, mx, 2));
            mx = fmaxf(mx, __shfl_xor_sync(0xffffffffu, mx, 4));
            mx = fmaxf(mx, __shfl_xor_sync(0xffffffffu, mx, 8));
            const float mnew  = fmaxf(mrow[ii], mx);
            const float alpha = ex2(mrow[ii] - mnew);
            mrow[ii] = mnew;
            float p0 = ex2(s0 - mnew);
            float p1 = ex2(s1 - mnew);
            float p2 = ex2(s2v - mnew);
            float p3 = ex2(s3 - mnew);
            float sum = p0 + p1 + p2 + p3;
            sum += __shfl_xor_sync(0xffffffffu, sum, 1);
            sum += __shfl_xor_sync(0xffffffffu, sum, 2);
            sum += __shfl_xor_sync(0xffffffffu, sum, 4);
            sum += __shfl_xor_sync(0xffffffffu, sum, 8);
            lrow[ii] = lrow[ii] * alpha + sum;
            ull ap = pk2(alpha);
            mul2(o2[ii][0], ap);
            mul2(o2[ii][1], ap);
            float* prow = KPd + (tr * 4 + ii) * 128 + 8 * tc;
            *(float4*)(prow)     = make_float4(p0, p0, p1, p1);
            *(float4*)(prow + 4) = make_float4(p2, p2, p3, p3);
        }
        __syncthreads();

#pragma unroll 4
        for (int j0 = 0; j0 < 64; j0 += 4) {
            ulonglong2 v[4];
#pragma unroll
            for (int jj = 0; jj < 4; jj++)
                v[jj] = *(const ulonglong2*)&Vs[(j0 + jj) * 64 + tc * 4];
#pragma unroll
            for (int ii = 0; ii < 4; ii++) {
                const float* prow = KPd + (tr * 4 + ii) * 128 + 2 * j0;
                ulonglong2 P0 = *(const ulonglong2*)(prow);
                ulonglong2 P1 = *(const ulonglong2*)(prow + 4);
                fma2(o2[ii][0], P0.x, v[0].x); fma2(o2[ii][1], P0.x, v[0].y);
                fma2(o2[ii][0], P0.y, v[1].x); fma2(o2[ii][1], P0.y, v[1].y);
                fma2(o2[ii][0], P1.x, v[2].x); fma2(o2[ii][1], P1.x, v[2].y);
                fma2(o2[ii][0], P1.y, v[3].x); fma2(o2[ii][1], P1.y, v[3].y);
            }
        }
    }

#pragma unroll
    for (int ii = 0; ii < 4; ii++) {
        const float inv = 1.0f / lrow[ii];
        float o0, o1, o2v, o3;
        unpk2(o2[ii][0], o0, o1);
        unpk2(o2[ii][1], o2v, o3);
        const int qg = qt * 64 + tr * 4 + ii;
        *(float4*)(O + ((size_t)b * 2048 + qg) * 1024 + h * 64 + tc * 4) =
            make_float4(o0 * inv, o1 * inv, o2v * inv, o3 * inv);
    }
}

// ================= launch =================
extern "C" void kernel_launch(void* const* d_in, const int* in_sizes, int n_in,
                              void* d_out, int out_size)
{
    const float* x  = (const float*)d_in[0];
    const float* wq = (const float*)d_in[1];
    const float* wk = (const float*)d_in[2];
    const float* wv = (const float*)d_in[3];
    const float* wo = (const float*)d_in[4];
    float* out = (float*)d_out;

    float *gQ, *gK, *gV, *gO;
    __nv_bfloat16 *xh, *xl, *oh, *ol, *wh, *wl;
    cudaGetSymbolAddress((void**)&gQ, g_Q);
    cudaGetSymbolAddress((void**)&gK, g_K);
    cudaGetSymbolAddress((void**)&gV, g_V);
    cudaGetSymbolAddress((void**)&gO, g_O);
    cudaGetSymbolAddress((void**)&xh, g_xh);
    cudaGetSymbolAddress((void**)&xl, g_xl);
    cudaGetSymbolAddress((void**)&oh, g_oh);
    cudaGetSymbolAddress((void**)&ol, g_ol);
    cudaGetSymbolAddress((void**)&wh, g_wh);
    cudaGetSymbolAddress((void**)&wl, g_wl);

    cudaFuncSetAttribute(mma_gemm, cudaFuncAttributeMaxDynamicSharedMemorySize, GEMM_SMEM_BYTES);
    cudaFuncSetAttribute(attn_k, cudaFuncAttributeMaxDynamicSharedMemorySize, ATTN_SMEM_BYTES);

    // bf16 hi/lo splits
    split_k<<<NELEM / 1024, 256>>>((const float4*)x, (__nv_bfloat162*)xh, (__nv_bfloat162*)xl, NELEM / 4);
    split_k<<<WELEM / 1024, 256>>>((const float4*)wq, (__nv_bfloat162*)(wh + 0 * WELEM), (__nv_bfloat162*)(wl + 0 * WELEM), WELEM / 4);
    split_k<<<WELEM / 1024, 256>>>((const float4*)wk, (__nv_bfloat162*)(wh + 1 * WELEM), (__nv_bfloat162*)(wl + 1 * WELEM), WELEM / 4);
    split_k<<<WELEM / 1024, 256>>>((const float4*)wv, (__nv_bfloat162*)(wh + 2 * WELEM), (__nv_bfloat162*)(wl + 2 * WELEM), WELEM / 4);
    split_k<<<WELEM / 1024, 256>>>((const float4*)wo, (__nv_bfloat162*)(wh + 3 * WELEM), (__nv_bfloat162*)(wl + 3 * WELEM), WELEM / 4);

    // Q/K (transposed out) + V (natural) projections via mma.sync
    mma_gemm<<<dim3(256, 1, 3), 256, GEMM_SMEM_BYTES>>>(xh, xl, wh, wl, gQ, gK, gV, /*ntrans=*/2);

    // causal flash attention (LPT grid)
    attn_k<<<dim3(16, 2, 32), 256, ATTN_SMEM_BYTES>>>(gQ, gK, gV, gO);

    // O-proj: split g_O, then natural GEMM with wo (weight slot 3)
    split_k<<<NELEM / 1024, 256>>>((const float4*)gO, (__nv_bfloat162*)oh, (__nv_bfloat162*)ol, NELEM / 4);
    mma_gemm<<<dim3(256, 1, 1), 256, GEMM_SMEM_BYTES>>>(oh, ol, wh + 3 * WELEM, wl + 3 * WELEM,
                                                        out, out, out, /*ntrans=*/0);
}